// round 3
// baseline (speedup 1.0000x reference)
#include <cuda_runtime.h>
#include <cuda_bf16.h>
#include <math.h>

#define D     512
#define KTOP  11          // 1 + K
#define KNEI  9           // reference uses idx[1:K] = 9 neighbors
#define NCLS  100
#define RPB   256         // rows per block in fused kernel
#define NMAX  250000
#define GMAX  ((NMAX + RPB - 1) / RPB)   // 977

// Scratch (allocation-free rule: __device__ globals)
__device__ unsigned long long g_cand[GMAX * KTOP];

// ---- monotonic float key: bigger key == bigger value; tie -> smaller index wins ----
__device__ __forceinline__ unsigned long long make_key(float v, unsigned int idx) {
    unsigned int b = __float_as_uint(v);
    b = (b & 0x80000000u) ? ~b : (b | 0x80000000u);
    return ((unsigned long long)b << 32) | (unsigned int)(~idx);
}
__device__ __forceinline__ float key_val(unsigned long long k) {
    unsigned int o = (unsigned int)(k >> 32);
    unsigned int b = (o & 0x80000000u) ? (o ^ 0x80000000u) : ~o;
    return __uint_as_float(b);
}
__device__ __forceinline__ unsigned int key_idx(unsigned long long k) {
    return ~(unsigned int)(k & 0xFFFFFFFFu);
}

__device__ __forceinline__ unsigned long long block_max_u64(unsigned long long v,
                                                            unsigned long long* sh) {
    #pragma unroll
    for (int o = 16; o; o >>= 1) {
        unsigned long long u = __shfl_xor_sync(0xFFFFFFFFu, v, o);
        if (u > v) v = u;
    }
    int warp = threadIdx.x >> 5, lane = threadIdx.x & 31;
    if (lane == 0) sh[warp] = v;
    __syncthreads();
    if (warp == 0) {
        int nw = (blockDim.x + 31) >> 5;
        v = (lane < nw) ? sh[lane] : 0ULL;
        #pragma unroll
        for (int o = 4; o; o >>= 1) {
            unsigned long long u = __shfl_xor_sync(0xFFFFFFFFu, v, o);
            if (u > v) v = u;
        }
        if (lane == 0) sh[0] = v;
    }
    __syncthreads();
    unsigned long long r = sh[0];
    __syncthreads();
    return r;
}

// ---------- Kernel 1: fused dot+sumsq streaming + per-block top-11 ----------
__global__ void __launch_bounds__(256) score_topk_kernel(
        const float* __restrict__ coll, const float* __restrict__ emb, int n) {
    __shared__ float4 sq[D / 4];
    __shared__ unsigned long long skeys[RPB];
    __shared__ unsigned long long sh[33];

    int t = threadIdx.x;
    if (t < D / 4) sq[t] = reinterpret_cast<const float4*>(emb)[t];
    skeys[t] = 0ULL;
    __syncthreads();

    int warp = t >> 5, lane = t & 31;
    int rbeg = blockIdx.x * RPB;
    int rend = min(rbeg + RPB, n);

    for (int it = 0; it < RPB / 8; it++) {
        int local = it * 8 + warp;
        int row = rbeg + local;
        if (row >= rend) break;
        const float4* rp = reinterpret_cast<const float4*>(coll + (size_t)row * D);
        float dot = 0.f, rr = 0.f;
        #pragma unroll
        for (int j = 0; j < 4; j++) {
            float4 v = __ldcs(rp + lane + 32 * j);   // streaming: no reuse, evict-first
            float4 q = sq[lane + 32 * j];
            dot += v.x * q.x + v.y * q.y + v.z * q.z + v.w * q.w;
            rr  += v.x * v.x + v.y * v.y + v.z * v.z + v.w * v.w;
        }
        #pragma unroll
        for (int o = 16; o; o >>= 1) {
            dot += __shfl_xor_sync(0xFFFFFFFFu, dot, o);
            rr  += __shfl_xor_sync(0xFFFFFFFFu, rr, o);
        }
        if (lane == 0)
            skeys[local] = make_key(dot * rsqrtf(rr + 1e-12f), (unsigned)row);
    }
    __syncthreads();

    // block top-11 over <=256 keys, one key per thread
    for (int r = 0; r < KTOP; r++) {
        unsigned long long v = skeys[t];
        unsigned long long w = block_max_u64(v, sh);
        if (t == 0) g_cand[blockIdx.x * KTOP + r] = w;
        if (skeys[t] == w) skeys[t] = 0ULL;      // keys unique (index embedded)
        __syncthreads();
    }
}

// ---------- Kernel 2: merge candidates, vote, write output ----------
__global__ void __launch_bounds__(256) finalize(
        const float* __restrict__ emb, const int* __restrict__ labels,
        float* __restrict__ out, int out_size, int ncand) {
    __shared__ unsigned long long sh[33];
    __shared__ unsigned long long top[KTOP];
    __shared__ float sred[8];

    // per-thread streaming top-11 (sorted descending in registers)
    unsigned long long loc[KTOP];
    #pragma unroll
    for (int i = 0; i < KTOP; i++) loc[i] = 0ULL;
    for (int i = threadIdx.x; i < ncand; i += 256) {
        unsigned long long k = g_cand[i];
        if (k > loc[KTOP - 1]) {
            int p = KTOP - 1;
            #pragma unroll
            for (int j = KTOP - 2; j >= 0; j--) {
                if (loc[j] < k) { loc[j + 1] = loc[j]; p = j; }
            }
            loc[p] = k;
        }
    }

    int ptr = 0;
    for (int r = 0; r < KTOP; r++) {
        unsigned long long v = (ptr < KTOP) ? loc[ptr] : 0ULL;
        unsigned long long w = block_max_u64(v, sh);
        if (threadIdx.x == 0) top[r] = w;
        if (ptr < KTOP && loc[ptr] == w) ptr++;
    }

    // ||q||^2
    float q0 = emb[threadIdx.x], q1 = emb[threadIdx.x + 256];
    float s = q0 * q0 + q1 * q1;
    #pragma unroll
    for (int o = 16; o; o >>= 1) s += __shfl_xor_sync(0xFFFFFFFFu, s, o);
    if ((threadIdx.x & 31) == 0) sred[threadIdx.x >> 5] = s;
    __syncthreads();

    if (threadIdx.x == 0) {
        float qq = 0.f;
        #pragma unroll
        for (int w = 0; w < 8; w++) qq += sred[w];
        float inv_q = 1.0f / sqrtf(qq + 1e-12f);

        float vals[KTOP]; int idxs[KTOP];
        #pragma unroll
        for (int i = 0; i < KTOP; i++) {
            vals[i] = key_val(top[i]) * inv_q;
            idxs[i] = (int)key_idx(top[i]);
        }
        int preds[KNEI];
        #pragma unroll
        for (int j = 0; j < KNEI; j++) preds[j] = labels[idxs[1 + j]];

        int counts[NCLS];
        #pragma unroll
        for (int c = 0; c < NCLS; c++) counts[c] = 0;
        #pragma unroll
        for (int j = 0; j < KNEI; j++) {
            int p = preds[j];
            if (p >= 0 && p < NCLS) counts[p]++;
        }
        int best = 0;
        for (int c = 1; c < NCLS; c++)
            if (counts[c] > counts[best]) best = c;   // first-occurrence argmax
        int pos = 0;
        for (int j = KNEI - 1; j >= 0; j--)
            if (preds[j] == best) pos = j;            // first match
        float conf = vals[1 + pos];

        int m = out_size < KTOP ? out_size : KTOP;
        for (int i = 0; i < m; i++) out[i] = vals[i];
        if (out_size > KTOP)     out[KTOP]     = (float)best;
        if (out_size > KTOP + 1) out[KTOP + 1] = conf;
        for (int i = KTOP + 2; i < out_size; i++) out[i] = 0.0f;
    }
}

extern "C" void kernel_launch(void* const* d_in, const int* in_sizes, int n_in,
                              void* d_out, int out_size) {
    const float* emb    = (const float*)d_in[0];
    const float* coll   = (const float*)d_in[1];
    const int*   labels = (const int*)d_in[2];   // jnp.int64 canonicalizes to int32 (no x64)
    int n = in_sizes[1] / D;   // 250000
    int grid = (n + RPB - 1) / RPB;              // 977

    score_topk_kernel<<<grid, 256>>>(coll, emb, n);
    finalize<<<1, 256>>>(emb, labels, (float*)d_out, out_size, grid * KTOP);
}

// round 4
// speedup vs baseline: 1.0147x; 1.0147x over previous
#include <cuda_runtime.h>
#include <cuda_bf16.h>
#include <math.h>

#define D     512
#define KTOP  11          // 1 + K
#define KNEI  9           // reference uses idx[1:K] = 9 neighbors
#define NCLS  100
#define RPB   512         // rows per block in fused kernel
#define NMAX  250000
#define GMAX  ((NMAX + RPB - 1) / RPB)   // 489
#define NCAND (GMAX * KTOP)              // 5379 keys = 43KB

// Scratch (allocation-free rule: __device__ globals)
__device__ unsigned long long g_cand[NCAND];

// ---- monotonic float key: bigger key == bigger value; tie -> smaller index wins ----
__device__ __forceinline__ unsigned long long make_key(float v, unsigned int idx) {
    unsigned int b = __float_as_uint(v);
    b = (b & 0x80000000u) ? ~b : (b | 0x80000000u);
    return ((unsigned long long)b << 32) | (unsigned int)(~idx);
}
__device__ __forceinline__ float key_val(unsigned long long k) {
    unsigned int o = (unsigned int)(k >> 32);
    unsigned int b = (o & 0x80000000u) ? (o ^ 0x80000000u) : ~o;
    return __uint_as_float(b);
}
__device__ __forceinline__ unsigned int key_idx(unsigned long long k) {
    return ~(unsigned int)(k & 0xFFFFFFFFu);
}

__device__ __forceinline__ unsigned long long block_max_u64(unsigned long long v,
                                                            unsigned long long* sh) {
    #pragma unroll
    for (int o = 16; o; o >>= 1) {
        unsigned long long u = __shfl_xor_sync(0xFFFFFFFFu, v, o);
        if (u > v) v = u;
    }
    int warp = threadIdx.x >> 5, lane = threadIdx.x & 31;
    if (lane == 0) sh[warp] = v;
    __syncthreads();
    if (warp == 0) {
        int nw = (blockDim.x + 31) >> 5;
        v = (lane < nw) ? sh[lane] : 0ULL;
        #pragma unroll
        for (int o = 4; o; o >>= 1) {
            unsigned long long u = __shfl_xor_sync(0xFFFFFFFFu, v, o);
            if (u > v) v = u;
        }
        if (lane == 0) sh[0] = v;
    }
    __syncthreads();
    unsigned long long r = sh[0];
    __syncthreads();
    return r;
}

// ---------- Kernel 1: fused dot+sumsq streaming + per-block top-11 over 512 rows ----------
__global__ void __launch_bounds__(256) score_topk_kernel(
        const float* __restrict__ coll, const float* __restrict__ emb, int n) {
    __shared__ float4 sq[D / 4];
    __shared__ unsigned long long skeys[RPB];
    __shared__ unsigned long long sh[33];

    int t = threadIdx.x;
    if (t < D / 4) sq[t] = reinterpret_cast<const float4*>(emb)[t];
    skeys[t] = 0ULL;
    skeys[t + 256] = 0ULL;
    __syncthreads();

    int warp = t >> 5, lane = t & 31;
    int rbeg = blockIdx.x * RPB;
    int rend = min(rbeg + RPB, n);

    for (int it = 0; it < RPB / 8; it++) {
        int local = it * 8 + warp;
        int row = rbeg + local;
        if (row >= rend) break;
        const float4* rp = reinterpret_cast<const float4*>(coll + (size_t)row * D);
        float dot = 0.f, rr = 0.f;
        #pragma unroll
        for (int j = 0; j < 4; j++) {
            float4 v = __ldcs(rp + lane + 32 * j);   // streaming: no reuse, evict-first
            float4 q = sq[lane + 32 * j];
            dot += v.x * q.x + v.y * q.y + v.z * q.z + v.w * q.w;
            rr  += v.x * v.x + v.y * v.y + v.z * v.z + v.w * v.w;
        }
        #pragma unroll
        for (int o = 16; o; o >>= 1) {
            dot += __shfl_xor_sync(0xFFFFFFFFu, dot, o);
            rr  += __shfl_xor_sync(0xFFFFFFFFu, rr, o);
        }
        if (lane == 0)
            skeys[local] = make_key(dot * rsqrtf(rr + 1e-12f), (unsigned)row);
    }
    __syncthreads();

    // block top-11 over 512 keys (2 per thread, pure max — no local arrays)
    for (int r = 0; r < KTOP; r++) {
        unsigned long long a = skeys[t], b = skeys[t + 256];
        unsigned long long m = a > b ? a : b;
        unsigned long long w = block_max_u64(m, sh);
        if (t == 0) g_cand[blockIdx.x * KTOP + r] = w;
        if (a == w) skeys[t] = 0ULL;            // keys unique (index embedded)
        if (b == w) skeys[t + 256] = 0ULL;
        __syncthreads();
    }
}

// ---------- Kernel 2: SMEM-resident merge of 5379 candidates, vote, output ----------
__global__ void __launch_bounds__(256) finalize(
        const float* __restrict__ emb, const int* __restrict__ labels,
        float* __restrict__ out, int out_size, int ncand) {
    __shared__ unsigned long long scand[NCAND];
    __shared__ unsigned long long sh[33];
    __shared__ unsigned long long top[KTOP];
    __shared__ float sred[8];

    int t = threadIdx.x;
    for (int i = t; i < NCAND; i += 256)
        scand[i] = (i < ncand) ? g_cand[i] : 0ULL;
    __syncthreads();

    for (int r = 0; r < KTOP; r++) {
        unsigned long long m = 0ULL; int am = -1;
        for (int i = t; i < NCAND; i += 256) {
            unsigned long long k = scand[i];
            if (k > m) { m = k; am = i; }
        }
        unsigned long long w = block_max_u64(m, sh);
        if (t == 0) top[r] = w;
        if (am >= 0 && m == w) scand[am] = 0ULL;  // keys unique: one owner
        __syncthreads();
    }

    // ||q||^2
    float q0 = emb[t], q1 = emb[t + 256];
    float s = q0 * q0 + q1 * q1;
    #pragma unroll
    for (int o = 16; o; o >>= 1) s += __shfl_xor_sync(0xFFFFFFFFu, s, o);
    if ((t & 31) == 0) sred[t >> 5] = s;
    __syncthreads();

    if (t == 0) {
        float qq = 0.f;
        #pragma unroll
        for (int w = 0; w < 8; w++) qq += sred[w];
        float inv_q = 1.0f / sqrtf(qq + 1e-12f);

        float vals[KTOP]; int idxs[KTOP];
        #pragma unroll
        for (int i = 0; i < KTOP; i++) {
            vals[i] = key_val(top[i]) * inv_q;
            idxs[i] = (int)key_idx(top[i]);
        }
        int preds[KNEI];
        #pragma unroll
        for (int j = 0; j < KNEI; j++) preds[j] = labels[idxs[1 + j]];

        int counts[NCLS];
        #pragma unroll
        for (int c = 0; c < NCLS; c++) counts[c] = 0;
        #pragma unroll
        for (int j = 0; j < KNEI; j++) {
            int p = preds[j];
            if (p >= 0 && p < NCLS) counts[p]++;
        }
        int best = 0;
        for (int c = 1; c < NCLS; c++)
            if (counts[c] > counts[best]) best = c;   // first-occurrence argmax
        int pos = 0;
        for (int j = KNEI - 1; j >= 0; j--)
            if (preds[j] == best) pos = j;            // first match
        float conf = vals[1 + pos];

        int m = out_size < KTOP ? out_size : KTOP;
        for (int i = 0; i < m; i++) out[i] = vals[i];
        if (out_size > KTOP)     out[KTOP]     = (float)best;
        if (out_size > KTOP + 1) out[KTOP + 1] = conf;
        for (int i = KTOP + 2; i < out_size; i++) out[i] = 0.0f;
    }
}

extern "C" void kernel_launch(void* const* d_in, const int* in_sizes, int n_in,
                              void* d_out, int out_size) {
    const float* emb    = (const float*)d_in[0];
    const float* coll   = (const float*)d_in[1];
    const int*   labels = (const int*)d_in[2];   // jnp.int64 canonicalizes to int32 (no x64)
    int n = in_sizes[1] / D;   // 250000
    int grid = (n + RPB - 1) / RPB;              // 489

    score_topk_kernel<<<grid, 256>>>(coll, emb, n);
    finalize<<<1, 256>>>(emb, labels, (float*)d_out, out_size, grid * KTOP);
}

// round 5
// speedup vs baseline: 1.1380x; 1.1215x over previous
#include <cuda_runtime.h>
#include <cuda_bf16.h>
#include <math.h>

#define D     512
#define KTOP  11          // 1 + K
#define KNEI  9           // reference uses idx[1:K] = 9 neighbors
#define NCLS  100
#define RPB   256         // rows per block in fused kernel (977 blocks -> good occupancy)
#define NMAX  250000
#define GMAX  ((NMAX + RPB - 1) / RPB)   // 977
#define NCAND (GMAX * KTOP)              // 10747
#define WSLICE 352                        // per-warp candidate slice in finalize (32*352 >= NCAND)

// Scratch (allocation-free rule: __device__ globals)
__device__ unsigned long long g_cand[NCAND];

// ---- monotonic float key: bigger key == bigger value; tie -> smaller index wins ----
__device__ __forceinline__ unsigned long long make_key(float v, unsigned int idx) {
    unsigned int b = __float_as_uint(v);
    b = (b & 0x80000000u) ? ~b : (b | 0x80000000u);
    return ((unsigned long long)b << 32) | (unsigned int)(~idx);
}
__device__ __forceinline__ float key_val(unsigned long long k) {
    unsigned int o = (unsigned int)(k >> 32);
    unsigned int b = (o & 0x80000000u) ? (o ^ 0x80000000u) : ~o;
    return __uint_as_float(b);
}
__device__ __forceinline__ unsigned int key_idx(unsigned long long k) {
    return ~(unsigned int)(k & 0xFFFFFFFFu);
}

__device__ __forceinline__ unsigned long long warp_max_u64(unsigned long long v) {
    #pragma unroll
    for (int o = 16; o; o >>= 1) {
        unsigned long long u = __shfl_xor_sync(0xFFFFFFFFu, v, o);
        if (u > v) v = u;
    }
    return v;
}

__device__ __forceinline__ unsigned long long block_max_u64(unsigned long long v,
                                                            unsigned long long* sh) {
    v = warp_max_u64(v);
    int warp = threadIdx.x >> 5, lane = threadIdx.x & 31;
    if (lane == 0) sh[warp] = v;
    __syncthreads();
    if (warp == 0) {
        int nw = (blockDim.x + 31) >> 5;
        v = (lane < nw) ? sh[lane] : 0ULL;
        #pragma unroll
        for (int o = 4; o; o >>= 1) {
            unsigned long long u = __shfl_xor_sync(0xFFFFFFFFu, v, o);
            if (u > v) v = u;
        }
        if (lane == 0) sh[0] = v;
    }
    __syncthreads();
    unsigned long long r = sh[0];
    __syncthreads();
    return r;
}

// ---------- Kernel 1: fused dot+sumsq streaming + per-block top-11 over 256 rows ----------
__global__ void __launch_bounds__(256) score_topk_kernel(
        const float* __restrict__ coll, const float* __restrict__ emb, int n) {
    __shared__ float4 sq[D / 4];
    __shared__ unsigned long long skeys[RPB];
    __shared__ unsigned long long sh[33];

    int t = threadIdx.x;
    if (t < D / 4) sq[t] = reinterpret_cast<const float4*>(emb)[t];
    skeys[t] = 0ULL;
    __syncthreads();

    int warp = t >> 5, lane = t & 31;
    int rbeg = blockIdx.x * RPB;
    int rend = min(rbeg + RPB, n);

    for (int it = 0; it < RPB / 8; it++) {
        int local = it * 8 + warp;
        int row = rbeg + local;
        if (row >= rend) break;
        const float4* rp = reinterpret_cast<const float4*>(coll + (size_t)row * D);
        float dot = 0.f, rr = 0.f;
        #pragma unroll
        for (int j = 0; j < 4; j++) {
            float4 v = __ldcs(rp + lane + 32 * j);   // streaming: no reuse, evict-first
            float4 q = sq[lane + 32 * j];
            dot += v.x * q.x + v.y * q.y + v.z * q.z + v.w * q.w;
            rr  += v.x * v.x + v.y * v.y + v.z * v.z + v.w * v.w;
        }
        #pragma unroll
        for (int o = 16; o; o >>= 1) {
            dot += __shfl_xor_sync(0xFFFFFFFFu, dot, o);
            rr  += __shfl_xor_sync(0xFFFFFFFFu, rr, o);
        }
        if (lane == 0)
            skeys[local] = make_key(dot * rsqrtf(rr + 1e-12f), (unsigned)row);
    }
    __syncthreads();

    // block top-11 over 256 keys
    for (int r = 0; r < KTOP; r++) {
        unsigned long long v = skeys[t];
        unsigned long long w = block_max_u64(v, sh);
        if (t == 0) g_cand[blockIdx.x * KTOP + r] = w;
        if (skeys[t] == w) skeys[t] = 0ULL;      // keys unique (index embedded)
        __syncthreads();
    }
}

// ---------- Kernel 2: register-resident two-stage warp merge, vote, output ----------
__global__ void __launch_bounds__(1024) finalize(
        const float* __restrict__ emb, const int* __restrict__ labels,
        float* __restrict__ out, int out_size, int ncand) {
    __shared__ unsigned long long swin[KTOP * 32];   // stage-1 winners: [round][warp]
    __shared__ unsigned long long top[KTOP];
    __shared__ float sred[32];

    int t = threadIdx.x;
    int warp = t >> 5, lane = t & 31;

    // Stage 1: each warp takes top-11 of its 352-key slice, keys in registers.
    unsigned long long k[KTOP];
    #pragma unroll
    for (int j = 0; j < KTOP; j++) {
        int i = warp * WSLICE + lane + j * 32;
        k[j] = (i < ncand) ? g_cand[i] : 0ULL;
    }
    #pragma unroll
    for (int r = 0; r < KTOP; r++) {
        unsigned long long m = k[0];
        #pragma unroll
        for (int j = 1; j < KTOP; j++) if (k[j] > m) m = k[j];
        unsigned long long w = warp_max_u64(m);
        if (lane == 0) swin[r * 32 + warp] = w;
        #pragma unroll
        for (int j = 0; j < KTOP; j++) if (k[j] == w) k[j] = 0ULL;
    }

    // ||q||^2 (all 32 warps participate; overlaps with nothing critical)
    {
        float q = (t < D) ? emb[t] : 0.f;
        float s = q * q;
        #pragma unroll
        for (int o = 16; o; o >>= 1) s += __shfl_xor_sync(0xFFFFFFFFu, s, o);
        if (lane == 0) sred[warp] = s;
    }
    __syncthreads();

    // Stage 2: warp 0 merges the 352 survivors (11 per lane, registers).
    if (warp == 0) {
        unsigned long long s2[KTOP];
        #pragma unroll
        for (int j = 0; j < KTOP; j++) s2[j] = swin[j * 32 + lane];
        #pragma unroll
        for (int r = 0; r < KTOP; r++) {
            unsigned long long m = s2[0];
            #pragma unroll
            for (int j = 1; j < KTOP; j++) if (s2[j] > m) m = s2[j];
            unsigned long long w = warp_max_u64(m);
            if (lane == 0) top[r] = w;
            #pragma unroll
            for (int j = 0; j < KTOP; j++) if (s2[j] == w) s2[j] = 0ULL;
        }
    }

    if (t == 0) {
        float qq = 0.f;
        #pragma unroll
        for (int w = 0; w < 32; w++) qq += sred[w];
        float inv_q = 1.0f / sqrtf(qq + 1e-12f);

        float vals[KTOP]; int idxs[KTOP];
        #pragma unroll
        for (int i = 0; i < KTOP; i++) {
            vals[i] = key_val(top[i]) * inv_q;
            idxs[i] = (int)key_idx(top[i]);
        }
        int preds[KNEI];
        #pragma unroll
        for (int j = 0; j < KNEI; j++) preds[j] = labels[idxs[1 + j]];

        int counts[NCLS];
        #pragma unroll
        for (int c = 0; c < NCLS; c++) counts[c] = 0;
        #pragma unroll
        for (int j = 0; j < KNEI; j++) {
            int p = preds[j];
            if (p >= 0 && p < NCLS) counts[p]++;
        }
        int best = 0;
        for (int c = 1; c < NCLS; c++)
            if (counts[c] > counts[best]) best = c;   // first-occurrence argmax
        int pos = 0;
        for (int j = KNEI - 1; j >= 0; j--)
            if (preds[j] == best) pos = j;            // first match
        float conf = vals[1 + pos];

        int m = out_size < KTOP ? out_size : KTOP;
        for (int i = 0; i < m; i++) out[i] = vals[i];
        if (out_size > KTOP)     out[KTOP]     = (float)best;
        if (out_size > KTOP + 1) out[KTOP + 1] = conf;
        for (int i = KTOP + 2; i < out_size; i++) out[i] = 0.0f;
    }
}

extern "C" void kernel_launch(void* const* d_in, const int* in_sizes, int n_in,
                              void* d_out, int out_size) {
    const float* emb    = (const float*)d_in[0];
    const float* coll   = (const float*)d_in[1];
    const int*   labels = (const int*)d_in[2];   // jnp.int64 canonicalizes to int32 (no x64)
    int n = in_sizes[1] / D;   // 250000
    int grid = (n + RPB - 1) / RPB;              // 977

    score_topk_kernel<<<grid, 256>>>(coll, emb, n);
    finalize<<<1, 1024>>>(emb, labels, (float*)d_out, out_size, grid * KTOP);
}